// round 7
// baseline (speedup 1.0000x reference)
#include <cuda_runtime.h>

// ---------------------------------------------------------------------------
// GCN, aggregate-first formulation:  conv(h) = (A_norm h) W + b
// Each layer = ONE kernel: warp-per-node CSR gather (edges pre-weighted,
// batch-loaded 32 at a time) -> per-node 64-wide GEMM via shfl broadcast
// -> fused bias+BN(eval)+ReLU -> write (or pool on the last layer).
// Feature layout: lane holds components (2*lane, 2*lane+1) as float2.
// ---------------------------------------------------------------------------

#define NN   100000
#define EE   1600000
#define GG   512
#define INF  26
#define HF   64
#define EPSV 1e-5f
#define FULL 0xffffffffu

__device__ float    g_h0[(size_t)NN * HF];
__device__ float    g_h1[(size_t)NN * HF];
__device__ int      g_deg[NN];
__device__ float    g_dinv[NN];
__device__ int      g_rowptr[NN + 1];
__device__ int      g_cursor[NN];
__device__ int2     g_pair[EE];            // (src, weight-bits) per CSR slot
__device__ int      g_bsum[128];
__device__ float    g_psum[GG * HF];
__device__ unsigned g_pmax[GG * HF];
__device__ int      g_pcnt[GG];

// --------------------------- setup ------------------------------------------

__global__ void init_kernel() {
    int i = blockIdx.x * blockDim.x + threadIdx.x;
    if (i < NN) g_deg[i] = 1;                         // self loop
    if (i < GG * HF) { g_psum[i] = 0.f; g_pmax[i] = 0u; }
    if (i < GG) g_pcnt[i] = 0;
}

__global__ void deg_kernel(const int* __restrict__ ecol) {
    int base = (blockIdx.x * blockDim.x + threadIdx.x) * 4;
    if (base + 3 < EE) {
        int4 c = *(const int4*)(ecol + base);
        atomicAdd(&g_deg[c.x], 1);
        atomicAdd(&g_deg[c.y], 1);
        atomicAdd(&g_deg[c.z], 1);
        atomicAdd(&g_deg[c.w], 1);
    } else {
        for (int e = base; e < EE; e++) atomicAdd(&g_deg[ecol[e]], 1);
    }
}

// Block-local exclusive scan of (deg-1) + dinv computation.
__global__ void scan1_kernel() {
    __shared__ int sbuf[1024];
    int t = threadIdx.x;
    int idx = blockIdx.x * 1024 + t;
    int d = (idx < NN) ? g_deg[idx] : 1;
    if (idx < NN) g_dinv[idx] = rsqrtf((float)d);
    int v = d - 1;                                    // real in-edges only
    sbuf[t] = v;
    __syncthreads();
    for (int off = 1; off < 1024; off <<= 1) {
        int tmp = (t >= off) ? sbuf[t - off] : 0;
        __syncthreads();
        sbuf[t] += tmp;
        __syncthreads();
    }
    if (idx < NN) g_rowptr[idx] = sbuf[t] - v;        // exclusive within block
    if (t == 1023) g_bsum[blockIdx.x] = sbuf[1023];
}

// Parallel exclusive scan of the (<=128) block sums.
__global__ void scan2_kernel(int nb) {
    __shared__ int sb[128];
    int t = threadIdx.x;
    int v = (t < nb) ? g_bsum[t] : 0;
    sb[t] = v;
    __syncthreads();
    for (int off = 1; off < 128; off <<= 1) {
        int tmp = (t >= off) ? sb[t - off] : 0;
        __syncthreads();
        sb[t] += tmp;
        __syncthreads();
    }
    if (t < nb) g_bsum[t] = sb[t] - v;                // exclusive
}

__global__ void scan3_kernel() {
    int idx = blockIdx.x * blockDim.x + threadIdx.x;
    if (idx < NN) {
        int rp = g_rowptr[idx] + g_bsum[idx >> 10];
        g_rowptr[idx] = rp;
        g_cursor[idx] = rp;
    }
    if (idx == 0) g_rowptr[NN] = EE;
}

// CSR fill with precomputed edge weight w = dinv[src]*dinv[dst].
__global__ void csr_kernel(const int* __restrict__ erow, const int* __restrict__ ecol) {
    int base = (blockIdx.x * blockDim.x + threadIdx.x) * 4;
    if (base + 3 < EE) {
        int4 r = *(const int4*)(erow + base);
        int4 c = *(const int4*)(ecol + base);
        int p0 = atomicAdd(&g_cursor[c.x], 1);
        int p1 = atomicAdd(&g_cursor[c.y], 1);
        int p2 = atomicAdd(&g_cursor[c.z], 1);
        int p3 = atomicAdd(&g_cursor[c.w], 1);
        g_pair[p0] = make_int2(r.x, __float_as_int(__ldg(&g_dinv[r.x]) * __ldg(&g_dinv[c.x])));
        g_pair[p1] = make_int2(r.y, __float_as_int(__ldg(&g_dinv[r.y]) * __ldg(&g_dinv[c.y])));
        g_pair[p2] = make_int2(r.z, __float_as_int(__ldg(&g_dinv[r.z]) * __ldg(&g_dinv[c.z])));
        g_pair[p3] = make_int2(r.w, __float_as_int(__ldg(&g_dinv[r.w]) * __ldg(&g_dinv[c.w])));
    } else {
        for (int e = base; e < EE; e++) {
            int c = ecol[e], r = erow[e];
            int pos = atomicAdd(&g_cursor[c], 1);
            g_pair[pos] = make_int2(r, __float_as_int(__ldg(&g_dinv[r]) * __ldg(&g_dinv[c])));
        }
    }
}

// ------------------------- fused layer kernel -------------------------------

template <int KIN, int POOL>
__global__ void layer_kernel(const float* __restrict__ hin,   // [N, KIN]
                             const float* __restrict__ W,     // [KIN, 64]
                             const float* __restrict__ bias,  // [64]
                             const float* __restrict__ bng, const float* __restrict__ bnb,
                             const float* __restrict__ bnm, const float* __restrict__ bnv,
                             int layer,
                             float* __restrict__ hout,        // [N, 64] (unused if POOL)
                             const int* __restrict__ batch) {
    __shared__ float Ws[KIN * HF];
    for (int i = threadIdx.x; i < KIN * HF; i += blockDim.x) Ws[i] = W[i];
    __syncthreads();

    int lane = threadIdx.x & 31;
    int warp = (blockIdx.x * blockDim.x + threadIdx.x) >> 5;
    int nw   = (gridDim.x * blockDim.x) >> 5;
    int per  = (NN + nw - 1) / nw;
    int i0 = warp * per;
    int i1 = min(NN, i0 + per);
    if (i0 >= NN) return;

    int c0 = 2 * lane, c1 = 2 * lane + 1;
    int o = layer * HF;
    float sc0 = bng[o + c0] * rsqrtf(bnv[o + c0] + EPSV);
    float sc1 = bng[o + c1] * rsqrtf(bnv[o + c1] + EPSV);
    float sh0 = (bias[c0] - bnm[o + c0]) * sc0 + bnb[o + c0];
    float sh1 = (bias[c1] - bnm[o + c1]) * sc1 + bnb[o + c1];

    // register-local pooling state (batch is sorted, chunks are contiguous)
    float ps0 = 0.f, ps1 = 0.f, pm0 = 0.f, pm1 = 0.f;
    int pcnt = 0, gcur = -1;

    int rpn = g_rowptr[i0];
    for (int i = i0; i < i1; i++) {
        int rp0 = rpn;
        rpn = g_rowptr[i + 1];
        float di = g_dinv[i];
        float di2 = di * di;

        float ox = 0.f, oy = 0.f;

        if (KIN == HF) {
            // ---- 64-dim aggregate: float2 per lane ----
            float2 acc;
            {
                float2 r = *(const float2*)&hin[(size_t)i * HF + c0];
                acc.x = di2 * r.x; acc.y = di2 * r.y;
            }
            int e = rp0;
            while (e < rpn) {
                int n = min(32, rpn - e);
                int2 p = (lane < n) ? __ldg(&g_pair[e + lane]) : make_int2(0, 0);
                if (n == 32) {
#pragma unroll 8
                    for (int k = 0; k < 32; k++) {
                        int s   = __shfl_sync(FULL, p.x, k);
                        float w = __int_as_float(__shfl_sync(FULL, p.y, k));
                        float2 r = *(const float2*)&hin[(size_t)s * HF + c0];
                        acc.x = fmaf(w, r.x, acc.x);
                        acc.y = fmaf(w, r.y, acc.y);
                    }
                } else {
                    for (int k = 0; k < n; k++) {
                        int s   = __shfl_sync(FULL, p.x, k);
                        float w = __int_as_float(__shfl_sync(FULL, p.y, k));
                        float2 r = *(const float2*)&hin[(size_t)s * HF + c0];
                        acc.x = fmaf(w, r.x, acc.x);
                        acc.y = fmaf(w, r.y, acc.y);
                    }
                }
                e += n;
            }
            // ---- per-node GEMM via shfl broadcast ----
#pragma unroll
            for (int j = 0; j < 32; j++) {
                float vx = __shfl_sync(FULL, acc.x, j);   // component 2j
                float vy = __shfl_sync(FULL, acc.y, j);   // component 2j+1
                float2 w0 = *(const float2*)&Ws[(2 * j)     * HF + c0];
                float2 w1 = *(const float2*)&Ws[(2 * j + 1) * HF + c0];
                ox = fmaf(vx, w0.x, ox); oy = fmaf(vx, w0.y, oy);
                ox = fmaf(vy, w1.x, ox); oy = fmaf(vy, w1.y, oy);
            }
        } else {
            // ---- 26-dim aggregate: one float per lane (lanes 0..25) ----
            float a = 0.f;
            if (lane < KIN) a = di2 * __ldg(&hin[(size_t)i * KIN + lane]);
            int e = rp0;
            while (e < rpn) {
                int n = min(32, rpn - e);
                int2 p = (lane < n) ? __ldg(&g_pair[e + lane]) : make_int2(0, 0);
                if (n == 32) {
#pragma unroll 8
                    for (int k = 0; k < 32; k++) {
                        int s   = __shfl_sync(FULL, p.x, k);
                        float w = __int_as_float(__shfl_sync(FULL, p.y, k));
                        float r = (lane < KIN) ? __ldg(&hin[(size_t)s * KIN + lane]) : 0.f;
                        a = fmaf(w, r, a);
                    }
                } else {
                    for (int k = 0; k < n; k++) {
                        int s   = __shfl_sync(FULL, p.x, k);
                        float w = __int_as_float(__shfl_sync(FULL, p.y, k));
                        float r = (lane < KIN) ? __ldg(&hin[(size_t)s * KIN + lane]) : 0.f;
                        a = fmaf(w, r, a);
                    }
                }
                e += n;
            }
#pragma unroll
            for (int k = 0; k < KIN; k++) {
                float v = __shfl_sync(FULL, a, k);
                float2 wv = *(const float2*)&Ws[k * HF + c0];
                ox = fmaf(v, wv.x, ox);
                oy = fmaf(v, wv.y, oy);
            }
        }

        // fused bias + BN(eval) + ReLU
        ox = fmaxf(fmaf(ox, sc0, sh0), 0.f);
        oy = fmaxf(fmaf(oy, sc1, sh1), 0.f);

        if (!POOL) {
            *(float2*)&hout[(size_t)i * HF + c0] = make_float2(ox, oy);
        } else {
            int g = batch[i];
            if (g != gcur) {
                if (gcur >= 0) {
                    atomicAdd(&g_psum[gcur * HF + c0], ps0);
                    atomicAdd(&g_psum[gcur * HF + c1], ps1);
                    atomicMax(&g_pmax[gcur * HF + c0], __float_as_uint(pm0));
                    atomicMax(&g_pmax[gcur * HF + c1], __float_as_uint(pm1));
                    if (lane == 0) atomicAdd(&g_pcnt[gcur], pcnt);
                }
                gcur = g; ps0 = ox; ps1 = oy; pm0 = ox; pm1 = oy; pcnt = 1;
            } else {
                ps0 += ox; ps1 += oy;
                pm0 = fmaxf(pm0, ox); pm1 = fmaxf(pm1, oy);
                pcnt++;
            }
        }
    }
    if (POOL && gcur >= 0) {
        atomicAdd(&g_psum[gcur * HF + c0], ps0);
        atomicAdd(&g_psum[gcur * HF + c1], ps1);
        atomicMax(&g_pmax[gcur * HF + c0], __float_as_uint(pm0));
        atomicMax(&g_pmax[gcur * HF + c1], __float_as_uint(pm1));
        if (lane == 0) atomicAdd(&g_pcnt[gcur], pcnt);
    }
}

// ------------------------------ head ----------------------------------------

__global__ void mlp_kernel(const float* __restrict__ Wc1, const float* __restrict__ bc1,
                           const float* __restrict__ Wc2, const float* __restrict__ bc2,
                           float* __restrict__ out) {
    int lane = threadIdx.x & 31;
    int g = (blockIdx.x * blockDim.x + threadIdx.x) >> 5;
    if (g >= GG) return;
    float inv = 1.0f / fmaxf((float)g_pcnt[g], 1.0f);
    float p0 = g_psum[g * HF + lane]      * inv;
    float p1 = g_psum[g * HF + lane + 32] * inv;
    float p2 = __uint_as_float(g_pmax[g * HF + lane]);
    float p3 = __uint_as_float(g_pmax[g * HF + lane + 32]);
    float h0 = bc1[lane], h1 = bc1[lane + 32];
#pragma unroll
    for (int k = 0; k < 32; k++) {
        float v0 = __shfl_sync(FULL, p0, k);
        float v1 = __shfl_sync(FULL, p1, k);
        float v2 = __shfl_sync(FULL, p2, k);
        float v3 = __shfl_sync(FULL, p3, k);
        h0 = fmaf(v0, Wc1[k * HF + lane], h0);
        h0 = fmaf(v1, Wc1[(k + 32) * HF + lane], h0);
        h0 = fmaf(v2, Wc1[(k + 64) * HF + lane], h0);
        h0 = fmaf(v3, Wc1[(k + 96) * HF + lane], h0);
        h1 = fmaf(v0, Wc1[k * HF + lane + 32], h1);
        h1 = fmaf(v1, Wc1[(k + 32) * HF + lane + 32], h1);
        h1 = fmaf(v2, Wc1[(k + 64) * HF + lane + 32], h1);
        h1 = fmaf(v3, Wc1[(k + 96) * HF + lane + 32], h1);
    }
    h0 = fmaxf(h0, 0.f);
    h1 = fmaxf(h1, 0.f);
    float o0 = h0 * Wc2[lane * 2 + 0] + h1 * Wc2[(lane + 32) * 2 + 0];
    float o1 = h0 * Wc2[lane * 2 + 1] + h1 * Wc2[(lane + 32) * 2 + 1];
#pragma unroll
    for (int off = 16; off; off >>= 1) {
        o0 += __shfl_down_sync(FULL, o0, off);
        o1 += __shfl_down_sync(FULL, o1, off);
    }
    if (lane == 0) {
        out[g * 2 + 0] = o0 + bc2[0];
        out[g * 2 + 1] = o1 + bc2[1];
    }
}

// ------------------------------ launch --------------------------------------

extern "C" void kernel_launch(void* const* d_in, const int* in_sizes, int n_in,
                              void* d_out, int out_size) {
    const float* x    = (const float*)d_in[0];
    const int*   erow = (const int*)d_in[1];
    const int*   ecol = (const int*)d_in[2];
    const int*   batch= (const int*)d_in[3];
    const float* W0   = (const float*)d_in[4];
    const float* b0   = (const float*)d_in[5];
    const float* W1   = (const float*)d_in[6];
    const float* b1   = (const float*)d_in[7];
    const float* W2   = (const float*)d_in[8];
    const float* b2   = (const float*)d_in[9];
    const float* bng  = (const float*)d_in[10];
    const float* bnb  = (const float*)d_in[11];
    const float* bnm  = (const float*)d_in[12];
    const float* bnv  = (const float*)d_in[13];
    const float* Wc1  = (const float*)d_in[14];
    const float* bc1  = (const float*)d_in[15];
    const float* Wc2  = (const float*)d_in[16];
    const float* bc2  = (const float*)d_in[17];
    float* out = (float*)d_out;

    // graph structure (all-int, cheap)
    init_kernel<<<(NN + 255) / 256, 256>>>();
    deg_kernel<<<(EE / 4 + 255) / 256, 256>>>(ecol);
    scan1_kernel<<<(NN + 1023) / 1024, 1024>>>();
    scan2_kernel<<<1, 128>>>((NN + 1023) / 1024);
    scan3_kernel<<<(NN + 255) / 256, 256>>>();
    csr_kernel<<<(EE / 4 + 255) / 256, 256>>>(erow, ecol);

    const int GB = 1184, BT = 256;   // 148 SMs x 8 blocks, 9472 warps
    layer_kernel<INF, 0><<<GB, BT>>>(x,    W0, b0, bng, bnb, bnm, bnv, 0, g_h0, batch);
    layer_kernel<HF,  0><<<GB, BT>>>(g_h0, W1, b1, bng, bnb, bnm, bnv, 1, g_h1, batch);
    layer_kernel<HF,  1><<<GB, BT>>>(g_h1, W2, b2, bng, bnb, bnm, bnv, 2, g_h0, batch);
    mlp_kernel<<<(GG * 32 + 255) / 256, 256>>>(Wc1, bc1, Wc2, bc2, out);
}

// round 8
// speedup vs baseline: 10.4939x; 10.4939x over previous
#include <cuda_runtime.h>

// ---------------------------------------------------------------------------
// GCN: 3x (GEMM -> GCN-normalized aggregate w/ self loops -> BN(eval)+ReLU)
//      -> global mean+max pool per graph -> 2-layer MLP head.
// R5 skeleton (proven 394us) + pre-weighted edge pairs: the aggregate's
// per-edge work is now 1 uniform int2 load (prefetched 2 ahead) + 2 coalesced
// row loads + 2 FMA. No dependent dinv load on the critical path.
// ---------------------------------------------------------------------------

#define NN   100000
#define EE   1600000
#define GG   512
#define INF  26
#define HF   64
#define EPSV 1e-5f
#define FULL 0xffffffffu

// Scratch (device globals; no runtime allocation allowed)
__device__ float    g_t[(size_t)NN * HF];   // transformed features (GEMM out)
__device__ float    g_h[(size_t)NN * HF];   // layer activations
__device__ int      g_deg[NN];              // in-degree incl. self loop
__device__ float    g_dinv[NN];             // deg^{-1/2}
__device__ int      g_rowptr[NN + 1];       // CSR row pointers (by target)
__device__ int      g_cursor[NN];           // fill cursors
__device__ int2     g_pair[EE];             // (src, weight-bits) per CSR slot
__device__ int      g_bsum[128];            // scan block sums
__device__ float    g_psum[GG * HF];        // pooling: sum
__device__ unsigned g_pmax[GG * HF];        // pooling: max (float bits, h>=0)
__device__ int      g_pcnt[GG];             // pooling: node count

// --------------------------- setup kernels --------------------------------

__global__ void init_kernel() {
    int i = blockIdx.x * blockDim.x + threadIdx.x;
    if (i < NN) g_deg[i] = 1;                       // self loop
    if (i < GG * HF) { g_psum[i] = 0.f; g_pmax[i] = 0u; }
    if (i < GG) g_pcnt[i] = 0;
}

__global__ void deg_kernel(const int* __restrict__ ecol) {
    int base = (blockIdx.x * blockDim.x + threadIdx.x) * 4;
    if (base + 3 < EE) {
        int4 c = *(const int4*)(ecol + base);
        atomicAdd(&g_deg[c.x], 1);
        atomicAdd(&g_deg[c.y], 1);
        atomicAdd(&g_deg[c.z], 1);
        atomicAdd(&g_deg[c.w], 1);
    } else {
        for (int e = base; e < EE; e++) atomicAdd(&g_deg[ecol[e]], 1);
    }
}

// Block-local exclusive scan of (deg-1) + dinv computation.
__global__ void scan1_kernel() {
    __shared__ int sbuf[1024];
    int t = threadIdx.x;
    int idx = blockIdx.x * 1024 + t;
    int d = (idx < NN) ? g_deg[idx] : 1;
    if (idx < NN) g_dinv[idx] = rsqrtf((float)d);
    int v = d - 1;                                  // real in-edges only
    sbuf[t] = v;
    __syncthreads();
    for (int off = 1; off < 1024; off <<= 1) {
        int tmp = (t >= off) ? sbuf[t - off] : 0;
        __syncthreads();
        sbuf[t] += tmp;
        __syncthreads();
    }
    if (idx < NN) g_rowptr[idx] = sbuf[t] - v;      // exclusive within block
    if (t == 1023) g_bsum[blockIdx.x] = sbuf[1023];
}

// Parallel exclusive scan of the (<=128) block sums.
__global__ void scan2_kernel(int nb) {
    __shared__ int sb[128];
    int t = threadIdx.x;
    int v = (t < nb) ? g_bsum[t] : 0;
    sb[t] = v;
    __syncthreads();
    for (int off = 1; off < 128; off <<= 1) {
        int tmp = (t >= off) ? sb[t - off] : 0;
        __syncthreads();
        sb[t] += tmp;
        __syncthreads();
    }
    if (t < nb) g_bsum[t] = sb[t] - v;              // exclusive
}

__global__ void scan3_kernel() {
    int idx = blockIdx.x * blockDim.x + threadIdx.x;
    if (idx < NN) {
        int rp = g_rowptr[idx] + g_bsum[idx >> 10];
        g_rowptr[idx] = rp;
        g_cursor[idx] = rp;
    }
    if (idx == 0) g_rowptr[NN] = EE;
}

// CSR fill with precomputed edge weight w = dinv[src]*dinv[dst].
__global__ void csr_kernel(const int* __restrict__ erow, const int* __restrict__ ecol) {
    int base = (blockIdx.x * blockDim.x + threadIdx.x) * 4;
    if (base + 3 < EE) {
        int4 r = *(const int4*)(erow + base);
        int4 c = *(const int4*)(ecol + base);
        int p0 = atomicAdd(&g_cursor[c.x], 1);
        int p1 = atomicAdd(&g_cursor[c.y], 1);
        int p2 = atomicAdd(&g_cursor[c.z], 1);
        int p3 = atomicAdd(&g_cursor[c.w], 1);
        g_pair[p0] = make_int2(r.x, __float_as_int(__ldg(&g_dinv[r.x]) * __ldg(&g_dinv[c.x])));
        g_pair[p1] = make_int2(r.y, __float_as_int(__ldg(&g_dinv[r.y]) * __ldg(&g_dinv[c.y])));
        g_pair[p2] = make_int2(r.z, __float_as_int(__ldg(&g_dinv[r.z]) * __ldg(&g_dinv[c.z])));
        g_pair[p3] = make_int2(r.w, __float_as_int(__ldg(&g_dinv[r.w]) * __ldg(&g_dinv[c.w])));
    } else {
        for (int e = base; e < EE; e++) {
            int c = ecol[e], r = erow[e];
            int pos = atomicAdd(&g_cursor[c], 1);
            g_pair[pos] = make_int2(r, __float_as_int(__ldg(&g_dinv[r]) * __ldg(&g_dinv[c])));
        }
    }
}

// ------------------------------ GEMM --------------------------------------
// Warp per node: t[node] = h[node] @ W, W staged in shared, input row
// distributed across lanes and broadcast via shfl. (Unchanged from R5.)
template <int K, bool FROM_GH>
__global__ void gemm_kernel(const float* __restrict__ hin, const float* __restrict__ W) {
    __shared__ float Ws[K * HF];
    for (int i = threadIdx.x; i < K * HF; i += blockDim.x) Ws[i] = W[i];
    __syncthreads();
    int lane = threadIdx.x & 31;
    int warp = (blockIdx.x * blockDim.x + threadIdx.x) >> 5;
    int nw   = (gridDim.x * blockDim.x) >> 5;
    const float* src = FROM_GH ? g_h : hin;
    for (int node = warp; node < NN; node += nw) {
        const float* hr = src + (size_t)node * K;
        float m0 = (K > 32 || lane < K) ? hr[lane] : 0.f;
        float m1 = (K > 32) ? hr[lane + 32] : 0.f;
        float a0 = 0.f, a1 = 0.f;
#pragma unroll
        for (int k = 0; k < K; k++) {
            float hv = (k < 32) ? __shfl_sync(FULL, m0, k)
                                : __shfl_sync(FULL, m1, k - 32);
            a0 = fmaf(hv, Ws[k * HF + lane], a0);
            a1 = fmaf(hv, Ws[k * HF + lane + 32], a1);
        }
        g_t[(size_t)node * HF + lane]      = a0;
        g_t[(size_t)node * HF + lane + 32] = a1;
    }
}

// --------------------------- aggregate ------------------------------------
// Warp per target node (strided). Per edge: one uniform int2 load (prefetched
// two ahead) + two coalesced row loads + two FMAs. Fused bias+BN+ReLU.
// Last layer feeds pooling atomics directly.
__global__ void agg_kernel(const float* __restrict__ bias,
                           const float* __restrict__ bng, const float* __restrict__ bnb,
                           const float* __restrict__ bnm, const float* __restrict__ bnv,
                           int layer, int do_pool, const int* __restrict__ batch) {
    int lane = threadIdx.x & 31;
    int warp = (blockIdx.x * blockDim.x + threadIdx.x) >> 5;
    int nw   = (gridDim.x * blockDim.x) >> 5;
    int o = layer * HF;
    float sc0 = bng[o + lane]      * rsqrtf(bnv[o + lane]      + EPSV);
    float sc1 = bng[o + lane + 32] * rsqrtf(bnv[o + lane + 32] + EPSV);
    float sh0 = (bias[lane]      - bnm[o + lane])      * sc0 + bnb[o + lane];
    float sh1 = (bias[lane + 32] - bnm[o + lane + 32]) * sc1 + bnb[o + lane + 32];

    for (int i = warp; i < NN; i += nw) {
        float di = __ldg(&g_dinv[i]);
        const float* ti = g_t + (size_t)i * HF;
        float a0 = di * di * ti[lane];
        float a1 = di * di * ti[lane + 32];
        int e   = __ldg(&g_rowptr[i]);
        int end = __ldg(&g_rowptr[i + 1]);
        // 2-deep software pipeline over pre-weighted edge pairs
        int2 p0 = make_int2(0, 0), p1 = make_int2(0, 0);
        if (e < end)     p0 = __ldg(&g_pair[e]);
        if (e + 1 < end) p1 = __ldg(&g_pair[e + 1]);
        for (; e < end; e++) {
            int   s = p0.x;
            float w = __int_as_float(p0.y);
            p0 = p1;
            if (e + 2 < end) p1 = __ldg(&g_pair[e + 2]);
            const float* ts = g_t + (size_t)s * HF;
            float t0 = __ldg(ts + lane);
            float t1 = __ldg(ts + lane + 32);
            a0 = fmaf(w, t0, a0);
            a1 = fmaf(w, t1, a1);
        }
        a0 = fmaxf(fmaf(a0, sc0, sh0), 0.f);
        a1 = fmaxf(fmaf(a1, sc1, sh1), 0.f);
        g_h[(size_t)i * HF + lane]      = a0;
        g_h[(size_t)i * HF + lane + 32] = a1;
        if (do_pool) {
            int g = __ldg(&batch[i]);
            atomicAdd(&g_psum[g * HF + lane], a0);
            atomicAdd(&g_psum[g * HF + lane + 32], a1);
            atomicMax(&g_pmax[g * HF + lane], __float_as_uint(a0));      // a>=0
            atomicMax(&g_pmax[g * HF + lane + 32], __float_as_uint(a1));
            if (lane == 0) atomicAdd(&g_pcnt[g], 1);
        }
    }
}

// ------------------------------ head ---------------------------------------

__global__ void mlp_kernel(const float* __restrict__ Wc1, const float* __restrict__ bc1,
                           const float* __restrict__ Wc2, const float* __restrict__ bc2,
                           float* __restrict__ out) {
    int lane = threadIdx.x & 31;
    int g = (blockIdx.x * blockDim.x + threadIdx.x) >> 5;
    if (g >= GG) return;
    float inv = 1.0f / fmaxf((float)g_pcnt[g], 1.0f);
    float p0 = g_psum[g * HF + lane]      * inv;           // mean[lane]
    float p1 = g_psum[g * HF + lane + 32] * inv;           // mean[lane+32]
    float p2 = __uint_as_float(g_pmax[g * HF + lane]);     // max[lane]
    float p3 = __uint_as_float(g_pmax[g * HF + lane + 32]);// max[lane+32]
    float h0 = bc1[lane], h1 = bc1[lane + 32];
#pragma unroll
    for (int k = 0; k < 32; k++) {
        float v0 = __shfl_sync(FULL, p0, k);
        float v1 = __shfl_sync(FULL, p1, k);
        float v2 = __shfl_sync(FULL, p2, k);
        float v3 = __shfl_sync(FULL, p3, k);
        h0 = fmaf(v0, Wc1[k * HF + lane], h0);
        h0 = fmaf(v1, Wc1[(k + 32) * HF + lane], h0);
        h0 = fmaf(v2, Wc1[(k + 64) * HF + lane], h0);
        h0 = fmaf(v3, Wc1[(k + 96) * HF + lane], h0);
        h1 = fmaf(v0, Wc1[k * HF + lane + 32], h1);
        h1 = fmaf(v1, Wc1[(k + 32) * HF + lane + 32], h1);
        h1 = fmaf(v2, Wc1[(k + 64) * HF + lane + 32], h1);
        h1 = fmaf(v3, Wc1[(k + 96) * HF + lane + 32], h1);
    }
    h0 = fmaxf(h0, 0.f);
    h1 = fmaxf(h1, 0.f);
    float o0 = h0 * Wc2[lane * 2 + 0] + h1 * Wc2[(lane + 32) * 2 + 0];
    float o1 = h0 * Wc2[lane * 2 + 1] + h1 * Wc2[(lane + 32) * 2 + 1];
#pragma unroll
    for (int off = 16; off; off >>= 1) {
        o0 += __shfl_down_sync(FULL, o0, off);
        o1 += __shfl_down_sync(FULL, o1, off);
    }
    if (lane == 0) {
        out[g * 2 + 0] = o0 + bc2[0];
        out[g * 2 + 1] = o1 + bc2[1];
    }
}

// ------------------------------ launch -------------------------------------

extern "C" void kernel_launch(void* const* d_in, const int* in_sizes, int n_in,
                              void* d_out, int out_size) {
    const float* x    = (const float*)d_in[0];
    const int*   erow = (const int*)d_in[1];
    const int*   ecol = (const int*)d_in[2];
    const int*   batch= (const int*)d_in[3];
    const float* W0   = (const float*)d_in[4];
    const float* b0   = (const float*)d_in[5];
    const float* W1   = (const float*)d_in[6];
    const float* b1   = (const float*)d_in[7];
    const float* W2   = (const float*)d_in[8];
    const float* b2   = (const float*)d_in[9];
    const float* bng  = (const float*)d_in[10];
    const float* bnb  = (const float*)d_in[11];
    const float* bnm  = (const float*)d_in[12];
    const float* bnv  = (const float*)d_in[13];
    const float* Wc1  = (const float*)d_in[14];
    const float* bc1  = (const float*)d_in[15];
    const float* Wc2  = (const float*)d_in[16];
    const float* bc2  = (const float*)d_in[17];
    float* out = (float*)d_out;

    // graph structure (recomputed every call; all-int, cheap)
    init_kernel<<<(NN + 255) / 256, 256>>>();
    deg_kernel<<<(EE / 4 + 255) / 256, 256>>>(ecol);
    scan1_kernel<<<(NN + 1023) / 1024, 1024>>>();
    scan2_kernel<<<1, 128>>>((NN + 1023) / 1024);
    scan3_kernel<<<(NN + 255) / 256, 256>>>();
    csr_kernel<<<(EE / 4 + 255) / 256, 256>>>(erow, ecol);

    const int GB = 2048, BT = 256;
    gemm_kernel<INF, false><<<GB, BT>>>(x, W0);
    agg_kernel<<<GB, BT>>>(b0, bng, bnb, bnm, bnv, 0, 0, batch);
    gemm_kernel<HF, true><<<GB, BT>>>(nullptr, W1);
    agg_kernel<<<GB, BT>>>(b1, bng, bnb, bnm, bnv, 1, 0, batch);
    gemm_kernel<HF, true><<<GB, BT>>>(nullptr, W2);
    agg_kernel<<<GB, BT>>>(b2, bng, bnb, bnm, bnv, 2, 1, batch);
    mlp_kernel<<<(GG * 32 + 255) / 256, 256>>>(Wc1, bc1, Wc2, bc2, out);
}

// round 9
// speedup vs baseline: 11.9265x; 1.1365x over previous
#include <cuda_runtime.h>

// ---------------------------------------------------------------------------
// GCN: 3x (GEMM -> GCN-normalized aggregate w/ self loops -> BN(eval)+ReLU)
//      -> global mean+max pool per graph -> 2-layer MLP head.
// R5 skeleton + (a) float2 feature layout (1 LDG.64 row load per edge),
// (b) packed fma.rn.f32x2 in aggregate + GEMMs, (c) self-cleaning state
// (no init kernel), gemm0 hoisted to the ncu capture slot.
// ---------------------------------------------------------------------------

#define NN   100000
#define EE   1600000
#define GG   512
#define INF  26
#define HF   64
#define EPSV 1e-5f
#define FULL 0xffffffffu

typedef unsigned long long ull;

// Scratch (device globals; zero-initialized at load, self-cleaned per call)
__device__ float2   g_t2[(size_t)NN * 32];  // transformed features [N,64]
__device__ float2   g_h2[(size_t)NN * 32];  // layer activations    [N,64]
__device__ int      g_deg[NN];              // edge-only in-degree (reset by scan1)
__device__ float    g_dinv[NN];             // (deg+1)^{-1/2}
__device__ int      g_rowptr[NN + 1];       // CSR row pointers (by target)
__device__ int      g_cursor[NN];           // fill cursors
__device__ int      g_csr[EE];              // source node per CSR slot
__device__ int      g_bsum[128];            // scan block sums
__device__ float    g_psum[GG * HF];        // pooling: sum   (reset by mlp)
__device__ unsigned g_pmax[GG * HF];        // pooling: max   (reset by mlp)
__device__ int      g_pcnt[GG];             // pooling: count (reset by mlp)

// ---------------------------- f32x2 helpers --------------------------------

__device__ __forceinline__ ull ffma2(ull a, ull b, ull c) {
    ull d;
    asm("fma.rn.f32x2 %0, %1, %2, %3;" : "=l"(d) : "l"(a), "l"(b), "l"(c));
    return d;
}
__device__ __forceinline__ ull pack2(float x, float y) {
    ull d;
    asm("mov.b64 %0, {%1, %2};" : "=l"(d) : "f"(x), "f"(y));
    return d;
}
__device__ __forceinline__ float2 unpack2(ull v) {
    float2 r;
    asm("mov.b64 {%0, %1}, %2;" : "=f"(r.x), "=f"(r.y) : "l"(v));
    return r;
}

// --------------------------- setup kernels ---------------------------------

__global__ void deg_kernel(const int* __restrict__ ecol) {
    int base = (blockIdx.x * blockDim.x + threadIdx.x) * 4;
    if (base + 3 < EE) {
        int4 c = *(const int4*)(ecol + base);
        atomicAdd(&g_deg[c.x], 1);
        atomicAdd(&g_deg[c.y], 1);
        atomicAdd(&g_deg[c.z], 1);
        atomicAdd(&g_deg[c.w], 1);
    } else {
        for (int e = base; e < EE; e++) atomicAdd(&g_deg[ecol[e]], 1);
    }
}

// Block-local exclusive scan of edge-degree + dinv; resets g_deg for next call.
__global__ void scan1_kernel() {
    __shared__ int sbuf[1024];
    int t = threadIdx.x;
    int idx = blockIdx.x * 1024 + t;
    int v = 0;
    if (idx < NN) {
        v = g_deg[idx];                    // edges only
        g_deg[idx] = 0;                    // self-clean for next call
        g_dinv[idx] = rsqrtf((float)(v + 1));   // +1 self loop
    }
    sbuf[t] = v;
    __syncthreads();
    for (int off = 1; off < 1024; off <<= 1) {
        int tmp = (t >= off) ? sbuf[t - off] : 0;
        __syncthreads();
        sbuf[t] += tmp;
        __syncthreads();
    }
    if (idx < NN) g_rowptr[idx] = sbuf[t] - v;   // exclusive within block
    if (t == 1023) g_bsum[blockIdx.x] = sbuf[1023];
}

__global__ void scan2_kernel(int nb) {
    __shared__ int sb[128];
    int t = threadIdx.x;
    int v = (t < nb) ? g_bsum[t] : 0;
    sb[t] = v;
    __syncthreads();
    for (int off = 1; off < 128; off <<= 1) {
        int tmp = (t >= off) ? sb[t - off] : 0;
        __syncthreads();
        sb[t] += tmp;
        __syncthreads();
    }
    if (t < nb) g_bsum[t] = sb[t] - v;           // exclusive
}

__global__ void scan3_kernel() {
    int idx = blockIdx.x * blockDim.x + threadIdx.x;
    if (idx < NN) {
        int rp = g_rowptr[idx] + g_bsum[idx >> 10];
        g_rowptr[idx] = rp;
        g_cursor[idx] = rp;
    }
    if (idx == 0) g_rowptr[NN] = EE;
}

__global__ void csr_kernel(const int* __restrict__ erow, const int* __restrict__ ecol) {
    int base = (blockIdx.x * blockDim.x + threadIdx.x) * 4;
    if (base + 3 < EE) {
        int4 r = *(const int4*)(erow + base);
        int4 c = *(const int4*)(ecol + base);
        g_csr[atomicAdd(&g_cursor[c.x], 1)] = r.x;
        g_csr[atomicAdd(&g_cursor[c.y], 1)] = r.y;
        g_csr[atomicAdd(&g_cursor[c.z], 1)] = r.z;
        g_csr[atomicAdd(&g_cursor[c.w], 1)] = r.w;
    } else {
        for (int e = base; e < EE; e++)
            g_csr[atomicAdd(&g_cursor[ecol[e]], 1)] = erow[e];
    }
}

// ------------------------------ GEMMs ---------------------------------------
// Layer 0: warp per node, K=26, FFMA2, output pair (2*lane, 2*lane+1).
__global__ void gemm26_kernel(const float* __restrict__ x, const float* __restrict__ W) {
    __shared__ __align__(16) float Ws[INF * HF];
    for (int i = threadIdx.x; i < INF * HF; i += blockDim.x) Ws[i] = W[i];
    __syncthreads();
    const ull* W64 = (const ull*)Ws;     // W64[k*32 + lane] = (W[k][2l], W[k][2l+1])
    int lane = threadIdx.x & 31;
    int warp = (blockIdx.x * blockDim.x + threadIdx.x) >> 5;
    int nw   = (gridDim.x * blockDim.x) >> 5;
    for (int node = warp; node < NN; node += nw) {
        float m = (lane < INF) ? __ldg(&x[(size_t)node * INF + lane]) : 0.f;
        ull acc = 0ull;                   // (0.f, 0.f)
#pragma unroll
        for (int k = 0; k < INF; k++) {
            float hv = __shfl_sync(FULL, m, k);
            acc = ffma2(pack2(hv, hv), W64[k * 32 + lane], acc);
        }
        g_t2[(size_t)node * 32 + lane] = unpack2(acc);
    }
}

// Layers 1,2: warp per 2 nodes, K=64, shared W LDS.64 amortized across nodes.
__global__ void gemm64_kernel(const float* __restrict__ W) {
    __shared__ __align__(16) float Ws[HF * HF];
    for (int i = threadIdx.x; i < HF * HF; i += blockDim.x) Ws[i] = W[i];
    __syncthreads();
    const ull* W64 = (const ull*)Ws;
    int lane = threadIdx.x & 31;
    int warp = (blockIdx.x * blockDim.x + threadIdx.x) >> 5;
    int nw   = (gridDim.x * blockDim.x) >> 5;
    const float* src = (const float*)g_h2;
    for (int nb = warp; nb < NN / 2; nb += nw) {
        const float* r0 = src + (size_t)(2 * nb) * HF;
        const float* r1 = r0 + HF;
        float a0 = r0[lane], b0 = r0[lane + 32];
        float a1 = r1[lane], b1 = r1[lane + 32];
        ull acc0 = 0ull, acc1 = 0ull;
#pragma unroll
        for (int k = 0; k < HF; k++) {
            float h0 = (k < 32) ? __shfl_sync(FULL, a0, k) : __shfl_sync(FULL, b0, k - 32);
            float h1 = (k < 32) ? __shfl_sync(FULL, a1, k) : __shfl_sync(FULL, b1, k - 32);
            ull w2 = W64[k * 32 + lane];
            acc0 = ffma2(pack2(h0, h0), w2, acc0);
            acc1 = ffma2(pack2(h1, h1), w2, acc1);
        }
        g_t2[(size_t)(2 * nb) * 32 + lane]     = unpack2(acc0);
        g_t2[(size_t)(2 * nb + 1) * 32 + lane] = unpack2(acc1);
    }
}

// --------------------------- aggregate --------------------------------------
// Warp per target node (strided). Per edge: uniform csr + uniform dinv loads
// (prefetched one ahead) + one coalesced LDG.64 row load + one FFMA2.
__global__ void agg_kernel(const float* __restrict__ bias,
                           const float* __restrict__ bng, const float* __restrict__ bnb,
                           const float* __restrict__ bnm, const float* __restrict__ bnv,
                           int layer, int do_pool, const int* __restrict__ batch) {
    int lane = threadIdx.x & 31;
    int warp = (blockIdx.x * blockDim.x + threadIdx.x) >> 5;
    int nw   = (gridDim.x * blockDim.x) >> 5;
    int c0 = 2 * lane, c1 = 2 * lane + 1;
    int o = layer * HF;
    float sc0 = bng[o + c0] * rsqrtf(bnv[o + c0] + EPSV);
    float sc1 = bng[o + c1] * rsqrtf(bnv[o + c1] + EPSV);
    float sh0 = (bias[c0] - bnm[o + c0]) * sc0 + bnb[o + c0];
    float sh1 = (bias[c1] - bnm[o + c1]) * sc1 + bnb[o + c1];

    for (int i = warp; i < NN; i += nw) {
        float di = __ldg(&g_dinv[i]);
        float di2 = di * di;
        float2 tt = g_t2[(size_t)i * 32 + lane];
        ull acc = pack2(di2 * tt.x, di2 * tt.y);
        int e   = __ldg(&g_rowptr[i]);
        int end = __ldg(&g_rowptr[i + 1]);
        if (e < end) {
            int s = __ldg(&g_csr[e]);
            float ds = __ldg(&g_dinv[s]);
            while (1) {
                ull rr = __ldg((const ull*)&g_t2[(size_t)s * 32 + lane]);
                float w = ds * di;
                e++;
                if (e < end) {                        // prefetch next edge
                    s = __ldg(&g_csr[e]);
                    ds = __ldg(&g_dinv[s]);
                }
                acc = ffma2(pack2(w, w), rr, acc);
                if (e >= end) break;
            }
        }
        float2 av = unpack2(acc);
        float o0 = fmaxf(fmaf(av.x, sc0, sh0), 0.f);
        float o1 = fmaxf(fmaf(av.y, sc1, sh1), 0.f);
        g_h2[(size_t)i * 32 + lane] = make_float2(o0, o1);
        if (do_pool) {
            int g = __ldg(&batch[i]);
            atomicAdd(&g_psum[g * HF + c0], o0);
            atomicAdd(&g_psum[g * HF + c1], o1);
            atomicMax(&g_pmax[g * HF + c0], __float_as_uint(o0));   // o>=0
            atomicMax(&g_pmax[g * HF + c1], __float_as_uint(o1));
            if (lane == 0) atomicAdd(&g_pcnt[g], 1);
        }
    }
}

// ------------------------------ head -----------------------------------------
// Warp per graph. Reads pooling state, then resets it for the next call.
__global__ void mlp_kernel(const float* __restrict__ Wc1, const float* __restrict__ bc1,
                           const float* __restrict__ Wc2, const float* __restrict__ bc2,
                           float* __restrict__ out) {
    int lane = threadIdx.x & 31;
    int g = (blockIdx.x * blockDim.x + threadIdx.x) >> 5;
    if (g >= GG) return;
    float inv = 1.0f / fmaxf((float)g_pcnt[g], 1.0f);
    float p0 = g_psum[g * HF + lane]      * inv;
    float p1 = g_psum[g * HF + lane + 32] * inv;
    float p2 = __uint_as_float(g_pmax[g * HF + lane]);
    float p3 = __uint_as_float(g_pmax[g * HF + lane + 32]);
    // self-clean pooling state for the next call
    g_psum[g * HF + lane] = 0.f;  g_psum[g * HF + lane + 32] = 0.f;
    g_pmax[g * HF + lane] = 0u;   g_pmax[g * HF + lane + 32] = 0u;
    if (lane == 0) g_pcnt[g] = 0;

    float h0 = bc1[lane], h1 = bc1[lane + 32];
#pragma unroll
    for (int k = 0; k < 32; k++) {
        float v0 = __shfl_sync(FULL, p0, k);
        float v1 = __shfl_sync(FULL, p1, k);
        float v2 = __shfl_sync(FULL, p2, k);
        float v3 = __shfl_sync(FULL, p3, k);
        h0 = fmaf(v0, Wc1[k * HF + lane], h0);
        h0 = fmaf(v1, Wc1[(k + 32) * HF + lane], h0);
        h0 = fmaf(v2, Wc1[(k + 64) * HF + lane], h0);
        h0 = fmaf(v3, Wc1[(k + 96) * HF + lane], h0);
        h1 = fmaf(v0, Wc1[k * HF + lane + 32], h1);
        h1 = fmaf(v1, Wc1[(k + 32) * HF + lane + 32], h1);
        h1 = fmaf(v2, Wc1[(k + 64) * HF + lane + 32], h1);
        h1 = fmaf(v3, Wc1[(k + 96) * HF + lane + 32], h1);
    }
    h0 = fmaxf(h0, 0.f);
    h1 = fmaxf(h1, 0.f);
    float o0 = h0 * Wc2[lane * 2 + 0] + h1 * Wc2[(lane + 32) * 2 + 0];
    float o1 = h0 * Wc2[lane * 2 + 1] + h1 * Wc2[(lane + 32) * 2 + 1];
#pragma unroll
    for (int off = 16; off; off >>= 1) {
        o0 += __shfl_down_sync(FULL, o0, off);
        o1 += __shfl_down_sync(FULL, o1, off);
    }
    if (lane == 0) {
        out[g * 2 + 0] = o0 + bc2[0];
        out[g * 2 + 1] = o1 + bc2[1];
    }
}

// ------------------------------ launch ---------------------------------------

extern "C" void kernel_launch(void* const* d_in, const int* in_sizes, int n_in,
                              void* d_out, int out_size) {
    const float* x    = (const float*)d_in[0];
    const int*   erow = (const int*)d_in[1];
    const int*   ecol = (const int*)d_in[2];
    const int*   batch= (const int*)d_in[3];
    const float* W0   = (const float*)d_in[4];
    const float* b0   = (const float*)d_in[5];
    const float* W1   = (const float*)d_in[6];
    const float* b1   = (const float*)d_in[7];
    const float* W2   = (const float*)d_in[8];
    const float* b2   = (const float*)d_in[9];
    const float* bng  = (const float*)d_in[10];
    const float* bnb  = (const float*)d_in[11];
    const float* bnm  = (const float*)d_in[12];
    const float* bnv  = (const float*)d_in[13];
    const float* Wc1  = (const float*)d_in[14];
    const float* bc1  = (const float*)d_in[15];
    const float* Wc2  = (const float*)d_in[16];
    const float* bc2  = (const float*)d_in[17];
    float* out = (float*)d_out;

    const int GB = 2048, BT = 256;

    // launches 1-3: degree + scan start
    deg_kernel<<<(EE / 4 + 255) / 256, 256>>>(ecol);
    scan1_kernel<<<(NN + 1023) / 1024, 1024>>>();
    scan2_kernel<<<1, 128>>>((NN + 1023) / 1024);
    // launch 4 (ncu capture slot): a hot kernel — gemm0 (independent of csr)
    gemm26_kernel<<<GB, BT>>>(x, W0);
    // launches 5-6: finish CSR
    scan3_kernel<<<(NN + 255) / 256, 256>>>();
    csr_kernel<<<(EE / 4 + 255) / 256, 256>>>(erow, ecol);
    // layers
    agg_kernel<<<GB, BT>>>(b0, bng, bnb, bnm, bnv, 0, 0, batch);
    gemm64_kernel<<<GB, BT>>>(W1);
    agg_kernel<<<GB, BT>>>(b1, bng, bnb, bnm, bnv, 1, 0, batch);
    gemm64_kernel<<<GB, BT>>>(W2);
    agg_kernel<<<GB, BT>>>(b2, bng, bnb, bnm, bnv, 2, 1, batch);
    mlp_kernel<<<(GG * 32 + 255) / 256, 256>>>(Wc1, bc1, Wc2, bc2, out);
}

// round 10
// speedup vs baseline: 14.2677x; 1.1963x over previous
#include <cuda_runtime.h>

// ---------------------------------------------------------------------------
// GCN: 3x (GEMM -> GCN-normalized aggregate w/ self loops -> BN(eval)+ReLU)
//      -> global mean+max pool per graph -> 2-layer MLP head.
// R8 skeleton (368us). This round: GEMMs restructured to warp-per-8-nodes,
// k-split FFMA2 (even/odd k partial sums in the two f32x2 halves), broadcast
// x-reads from a staged shared tile, W staged as k-pairs. No shuffles, LDS
// crossbar traffic cut ~4x; kernels become FFMA2-floor bound.
// Aggregate / setup / mlp byte-identical to R8.
// ---------------------------------------------------------------------------

#define NN   100000
#define EE   1600000
#define GG   512
#define INF  26
#define HF   64
#define EPSV 1e-5f
#define FULL 0xffffffffu

typedef unsigned long long ull;

// Scratch (device globals; zero-initialized at load, self-cleaned per call)
__device__ float2   g_t2[(size_t)NN * 32];  // transformed features [N,64]
__device__ float2   g_h2[(size_t)NN * 32];  // layer activations    [N,64]
__device__ int      g_deg[NN];              // edge-only in-degree (reset by scan1)
__device__ float    g_dinv[NN];             // (deg+1)^{-1/2}
__device__ int      g_rowptr[NN + 1];       // CSR row pointers (by target)
__device__ int      g_cursor[NN];           // fill cursors
__device__ int      g_csr[EE];              // source node per CSR slot
__device__ int      g_bsum[128];            // scan block sums
__device__ float    g_psum[GG * HF];        // pooling: sum   (reset by mlp)
__device__ unsigned g_pmax[GG * HF];        // pooling: max   (reset by mlp)
__device__ int      g_pcnt[GG];             // pooling: count (reset by mlp)

// ---------------------------- f32x2 helpers --------------------------------

__device__ __forceinline__ ull ffma2(ull a, ull b, ull c) {
    ull d;
    asm("fma.rn.f32x2 %0, %1, %2, %3;" : "=l"(d) : "l"(a), "l"(b), "l"(c));
    return d;
}
__device__ __forceinline__ ull pack2(float x, float y) {
    ull d;
    asm("mov.b64 %0, {%1, %2};" : "=l"(d) : "f"(x), "f"(y));
    return d;
}
__device__ __forceinline__ float2 unpack2(ull v) {
    float2 r;
    asm("mov.b64 {%0, %1}, %2;" : "=f"(r.x), "=f"(r.y) : "l"(v));
    return r;
}

// --------------------------- setup kernels ---------------------------------

__global__ void deg_kernel(const int* __restrict__ ecol) {
    int base = (blockIdx.x * blockDim.x + threadIdx.x) * 4;
    if (base + 3 < EE) {
        int4 c = *(const int4*)(ecol + base);
        atomicAdd(&g_deg[c.x], 1);
        atomicAdd(&g_deg[c.y], 1);
        atomicAdd(&g_deg[c.z], 1);
        atomicAdd(&g_deg[c.w], 1);
    } else {
        for (int e = base; e < EE; e++) atomicAdd(&g_deg[ecol[e]], 1);
    }
}

__global__ void scan1_kernel() {
    __shared__ int sbuf[1024];
    int t = threadIdx.x;
    int idx = blockIdx.x * 1024 + t;
    int v = 0;
    if (idx < NN) {
        v = g_deg[idx];                         // edges only
        g_deg[idx] = 0;                         // self-clean for next call
        g_dinv[idx] = rsqrtf((float)(v + 1));   // +1 self loop
    }
    sbuf[t] = v;
    __syncthreads();
    for (int off = 1; off < 1024; off <<= 1) {
        int tmp = (t >= off) ? sbuf[t - off] : 0;
        __syncthreads();
        sbuf[t] += tmp;
        __syncthreads();
    }
    if (idx < NN) g_rowptr[idx] = sbuf[t] - v;
    if (t == 1023) g_bsum[blockIdx.x] = sbuf[1023];
}

__global__ void scan2_kernel(int nb) {
    __shared__ int sb[128];
    int t = threadIdx.x;
    int v = (t < nb) ? g_bsum[t] : 0;
    sb[t] = v;
    __syncthreads();
    for (int off = 1; off < 128; off <<= 1) {
        int tmp = (t >= off) ? sb[t - off] : 0;
        __syncthreads();
        sb[t] += tmp;
        __syncthreads();
    }
    if (t < nb) g_bsum[t] = sb[t] - v;
}

__global__ void scan3_kernel() {
    int idx = blockIdx.x * blockDim.x + threadIdx.x;
    if (idx < NN) {
        int rp = g_rowptr[idx] + g_bsum[idx >> 10];
        g_rowptr[idx] = rp;
        g_cursor[idx] = rp;
    }
    if (idx == 0) g_rowptr[NN] = EE;
}

__global__ void csr_kernel(const int* __restrict__ erow, const int* __restrict__ ecol) {
    int base = (blockIdx.x * blockDim.x + threadIdx.x) * 4;
    if (base + 3 < EE) {
        int4 r = *(const int4*)(erow + base);
        int4 c = *(const int4*)(ecol + base);
        g_csr[atomicAdd(&g_cursor[c.x], 1)] = r.x;
        g_csr[atomicAdd(&g_cursor[c.y], 1)] = r.y;
        g_csr[atomicAdd(&g_cursor[c.z], 1)] = r.z;
        g_csr[atomicAdd(&g_cursor[c.w], 1)] = r.w;
    } else {
        for (int e = base; e < EE; e++)
            g_csr[atomicAdd(&g_cursor[ecol[e]], 1)] = erow[e];
    }
}

// ------------------------------ GEMMs ---------------------------------------
// Layer 0 GEMM: block = 64 nodes, warp = 8 nodes. K=26 padded to 28.
// Wp[k2*64+c] = (W[2k2][c], W[2k2+1][c]); x staged as padded pair rows.
// ffma2 accumulates even/odd-k partials in the two halves; FADD merges.
__global__ void gemm26_kernel(const float* __restrict__ x, const float* __restrict__ W) {
    __shared__ __align__(16) ull  Wp[14 * HF];     // 7 KB
    __shared__ __align__(16) float xsf[64 * 28];   // 7 KB
    int tid = threadIdx.x;
    for (int i = tid; i < 14 * HF; i += 256) {
        int k2 = i >> 6, c = i & 63;
        float w0 = (2 * k2     < INF) ? W[(2 * k2)     * HF + c] : 0.f;
        float w1 = (2 * k2 + 1 < INF) ? W[(2 * k2 + 1) * HF + c] : 0.f;
        Wp[i] = pack2(w0, w1);
    }
    int base = blockIdx.x * 64;
    int cnt = min(64, NN - base);
    for (int i = tid; i < cnt * 28; i += 256) {
        int row = i / 28, col = i - row * 28;
        xsf[i] = (col < INF) ? __ldg(&x[(size_t)(base + row) * INF + col]) : 0.f;
    }
    __syncthreads();

    int lane = tid & 31;
    int n0 = (tid >> 5) * 8;                       // node group within block
    if (n0 >= cnt) return;
    const longlong2* X4 = (const longlong2*)xsf;   // [node*7 + k4] = 4 x values

    ull a0[8], a1[8];
#pragma unroll
    for (int n = 0; n < 8; n++) { a0[n] = 0ull; a1[n] = 0ull; }
#pragma unroll
    for (int k4 = 0; k4 < 7; k4++) {
        ull w00 = Wp[(2 * k4) * HF + lane];
        ull w01 = Wp[(2 * k4) * HF + 32 + lane];
        ull w10 = Wp[(2 * k4 + 1) * HF + lane];
        ull w11 = Wp[(2 * k4 + 1) * HF + 32 + lane];
#pragma unroll
        for (int n = 0; n < 8; n++) {
            longlong2 xq = X4[(n0 + n) * 7 + k4];  // broadcast LDS.128
            a0[n] = ffma2((ull)xq.x, w00, a0[n]);
            a1[n] = ffma2((ull)xq.x, w01, a1[n]);
            a0[n] = ffma2((ull)xq.y, w10, a0[n]);
            a1[n] = ffma2((ull)xq.y, w11, a1[n]);
        }
    }
    float* dst = (float*)g_t2;
#pragma unroll
    for (int n = 0; n < 8; n++) {
        int node = base + n0 + n;
        if (node < NN) {
            float2 v0 = unpack2(a0[n]);
            float2 v1 = unpack2(a1[n]);
            dst[(size_t)node * HF + lane]      = v0.x + v0.y;
            dst[(size_t)node * HF + lane + 32] = v1.x + v1.y;
        }
    }
}

// Layers 1,2 GEMM: block = 64 nodes, warp = 8 nodes, K=64 (16 k4 steps).
__global__ void gemm64_kernel(const float* __restrict__ W) {
    __shared__ __align__(16) ull Wp[32 * HF];      // 16 KB
    __shared__ __align__(16) ull xs2[64 * 32];     // 16 KB
    int tid = threadIdx.x;
    for (int i = tid; i < 32 * HF; i += 256) {
        int k2 = i >> 6, c = i & 63;
        Wp[i] = pack2(W[(2 * k2) * HF + c], W[(2 * k2 + 1) * HF + c]);
    }
    int base = blockIdx.x * 64;
    int cnt = min(64, NN - base);
    const ull* src = (const ull*)(g_h2 + (size_t)base * 32);
    for (int i = tid; i < cnt * 32; i += 256) xs2[i] = src[i];
    __syncthreads();

    int lane = tid & 31;
    int n0 = (tid >> 5) * 8;
    if (n0 >= cnt) return;
    const longlong2* X4 = (const longlong2*)xs2;   // [node*16 + k4]

    ull a0[8], a1[8];
#pragma unroll
    for (int n = 0; n < 8; n++) { a0[n] = 0ull; a1[n] = 0ull; }
#pragma unroll
    for (int k4 = 0; k4 < 16; k4++) {
        ull w00 = Wp[(2 * k4) * HF + lane];
        ull w01 = Wp[(2 * k4) * HF + 32 + lane];
        ull w10 = Wp[(2 * k4 + 1) * HF + lane];
        ull w11 = Wp[(2 * k4 + 1) * HF + 32 + lane];
#pragma unroll
        for (int n = 0; n < 8; n++) {
            longlong2 xq = X4[(n0 + n) * 16 + k4]; // broadcast LDS.128
            a0[n] = ffma2((ull)xq.x, w00, a0[n]);
            a1[n] = ffma2((ull)xq.x, w01, a1[n]);
            a0[n] = ffma2((ull)xq.y, w10, a0[n]);
            a1[n] = ffma2((ull)xq.y, w11, a1[n]);
        }
    }
    float* dst = (float*)g_t2;
#pragma unroll
    for (int n = 0; n < 8; n++) {
        int node = base + n0 + n;
        if (node < NN) {
            float2 v0 = unpack2(a0[n]);
            float2 v1 = unpack2(a1[n]);
            dst[(size_t)node * HF + lane]      = v0.x + v0.y;
            dst[(size_t)node * HF + lane + 32] = v1.x + v1.y;
        }
    }
}

// --------------------------- aggregate --------------------------------------
// (Byte-identical to R8.) Warp per target node; per edge: uniform csr+dinv
// loads (prefetched one ahead) + one coalesced LDG.64 row load + one FFMA2.
__global__ void agg_kernel(const float* __restrict__ bias,
                           const float* __restrict__ bng, const float* __restrict__ bnb,
                           const float* __restrict__ bnm, const float* __restrict__ bnv,
                           int layer, int do_pool, const int* __restrict__ batch) {
    int lane = threadIdx.x & 31;
    int warp = (blockIdx.x * blockDim.x + threadIdx.x) >> 5;
    int nw   = (gridDim.x * blockDim.x) >> 5;
    int c0 = 2 * lane, c1 = 2 * lane + 1;
    int o = layer * HF;
    float sc0 = bng[o + c0] * rsqrtf(bnv[o + c0] + EPSV);
    float sc1 = bng[o + c1] * rsqrtf(bnv[o + c1] + EPSV);
    float sh0 = (bias[c0] - bnm[o + c0]) * sc0 + bnb[o + c0];
    float sh1 = (bias[c1] - bnm[o + c1]) * sc1 + bnb[o + c1];

    for (int i = warp; i < NN; i += nw) {
        float di = __ldg(&g_dinv[i]);
        float di2 = di * di;
        float2 tt = g_t2[(size_t)i * 32 + lane];
        ull acc = pack2(di2 * tt.x, di2 * tt.y);
        int e   = __ldg(&g_rowptr[i]);
        int end = __ldg(&g_rowptr[i + 1]);
        if (e < end) {
            int s = __ldg(&g_csr[e]);
            float ds = __ldg(&g_dinv[s]);
            while (1) {
                ull rr = __ldg((const ull*)&g_t2[(size_t)s * 32 + lane]);
                float w = ds * di;
                e++;
                if (e < end) {
                    s = __ldg(&g_csr[e]);
                    ds = __ldg(&g_dinv[s]);
                }
                acc = ffma2(pack2(w, w), rr, acc);
                if (e >= end) break;
            }
        }
        float2 av = unpack2(acc);
        float o0 = fmaxf(fmaf(av.x, sc0, sh0), 0.f);
        float o1 = fmaxf(fmaf(av.y, sc1, sh1), 0.f);
        g_h2[(size_t)i * 32 + lane] = make_float2(o0, o1);
        if (do_pool) {
            int g = __ldg(&batch[i]);
            atomicAdd(&g_psum[g * HF + c0], o0);
            atomicAdd(&g_psum[g * HF + c1], o1);
            atomicMax(&g_pmax[g * HF + c0], __float_as_uint(o0));
            atomicMax(&g_pmax[g * HF + c1], __float_as_uint(o1));
            if (lane == 0) atomicAdd(&g_pcnt[g], 1);
        }
    }
}

// ------------------------------ head -----------------------------------------

__global__ void mlp_kernel(const float* __restrict__ Wc1, const float* __restrict__ bc1,
                           const float* __restrict__ Wc2, const float* __restrict__ bc2,
                           float* __restrict__ out) {
    int lane = threadIdx.x & 31;
    int g = (blockIdx.x * blockDim.x + threadIdx.x) >> 5;
    if (g >= GG) return;
    float inv = 1.0f / fmaxf((float)g_pcnt[g], 1.0f);
    float p0 = g_psum[g * HF + lane]      * inv;
    float p1 = g_psum[g * HF + lane + 32] * inv;
    float p2 = __uint_as_float(g_pmax[g * HF + lane]);
    float p3 = __uint_as_float(g_pmax[g * HF + lane + 32]);
    g_psum[g * HF + lane] = 0.f;  g_psum[g * HF + lane + 32] = 0.f;
    g_pmax[g * HF + lane] = 0u;   g_pmax[g * HF + lane + 32] = 0u;
    if (lane == 0) g_pcnt[g] = 0;

    float h0 = bc1[lane], h1 = bc1[lane + 32];
#pragma unroll
    for (int k = 0; k < 32; k++) {
        float v0 = __shfl_sync(FULL, p0, k);
        float v1 = __shfl_sync(FULL, p1, k);
        float v2 = __shfl_sync(FULL, p2, k);
        float v3 = __shfl_sync(FULL, p3, k);
        h0 = fmaf(v0, Wc1[k * HF + lane], h0);
        h0 = fmaf(v1, Wc1[(k + 32) * HF + lane], h0);
        h0 = fmaf(v2, Wc1[(k + 64) * HF + lane], h0);
        h0 = fmaf(v3, Wc1[(k + 96) * HF + lane], h0);
        h1 = fmaf(v0, Wc1[k * HF + lane + 32], h1);
        h1 = fmaf(v1, Wc1[(k + 32) * HF + lane + 32], h1);
        h1 = fmaf(v2, Wc1[(k + 64) * HF + lane + 32], h1);
        h1 = fmaf(v3, Wc1[(k + 96) * HF + lane + 32], h1);
    }
    h0 = fmaxf(h0, 0.f);
    h1 = fmaxf(h1, 0.f);
    float o0 = h0 * Wc2[lane * 2 + 0] + h1 * Wc2[(lane + 32) * 2 + 0];
    float o1 = h0 * Wc2[lane * 2 + 1] + h1 * Wc2[(lane + 32) * 2 + 1];
#pragma unroll
    for (int off = 16; off; off >>= 1) {
        o0 += __shfl_down_sync(FULL, o0, off);
        o1 += __shfl_down_sync(FULL, o1, off);
    }
    if (lane == 0) {
        out[g * 2 + 0] = o0 + bc2[0];
        out[g * 2 + 1] = o1 + bc2[1];
    }
}

// ------------------------------ launch ---------------------------------------

extern "C" void kernel_launch(void* const* d_in, const int* in_sizes, int n_in,
                              void* d_out, int out_size) {
    const float* x    = (const float*)d_in[0];
    const int*   erow = (const int*)d_in[1];
    const int*   ecol = (const int*)d_in[2];
    const int*   batch= (const int*)d_in[3];
    const float* W0   = (const float*)d_in[4];
    const float* b0   = (const float*)d_in[5];
    const float* W1   = (const float*)d_in[6];
    const float* b1   = (const float*)d_in[7];
    const float* W2   = (const float*)d_in[8];
    const float* b2   = (const float*)d_in[9];
    const float* bng  = (const float*)d_in[10];
    const float* bnb  = (const float*)d_in[11];
    const float* bnm  = (const float*)d_in[12];
    const float* bnv  = (const float*)d_in[13];
    const float* Wc1  = (const float*)d_in[14];
    const float* bc1  = (const float*)d_in[15];
    const float* Wc2  = (const float*)d_in[16];
    const float* bc2  = (const float*)d_in[17];
    float* out = (float*)d_out;

    const int GB = 2048, BT = 256;
    const int GEMM_BLOCKS = (NN + 63) / 64;   // 64 nodes per block

    deg_kernel<<<(EE / 4 + 255) / 256, 256>>>(ecol);
    scan1_kernel<<<(NN + 1023) / 1024, 1024>>>();
    scan2_kernel<<<1, 128>>>((NN + 1023) / 1024);
    // launch 4 = ncu capture slot: the rebuilt gemm26
    gemm26_kernel<<<GEMM_BLOCKS, 256>>>(x, W0);
    scan3_kernel<<<(NN + 255) / 256, 256>>>();
    csr_kernel<<<(EE / 4 + 255) / 256, 256>>>(erow, ecol);

    agg_kernel<<<GB, BT>>>(b0, bng, bnb, bnm, bnv, 0, 0, batch);
    gemm64_kernel<<<GEMM_BLOCKS, 256>>>(W1);
    agg_kernel<<<GB, BT>>>(b1, bng, bnb, bnm, bnv, 1, 0, batch);
    gemm64_kernel<<<GEMM_BLOCKS, 256>>>(W2);
    agg_kernel<<<GB, BT>>>(b2, bng, bnb, bnm, bnv, 2, 1, batch);
    mlp_kernel<<<(GG * 32 + 255) / 256, 256>>>(Wc1, bc1, Wc2, bc2, out);
}